// round 3
// baseline (speedup 1.0000x reference)
#include <cuda_runtime.h>
#include <cuda_bf16.h>

#define N_NODES 100000
#define N_EDGES 3200000
#define IN_CH   512
#define OUT_CH  64

// ---- scratch: __device__ globals only (no allocations allowed) ----
__device__ int g_is64;
__device__ __align__(16) int   g_rows  [N_EDGES];
__device__ __align__(16) int   g_cols  [N_EDGES];
__device__ __align__(16) int   g_cnt   [N_NODES];
__device__ __align__(16) int   g_rowptr[N_NODES + 1];
__device__ __align__(16) float g_dinv  [N_NODES];
__device__ __align__(16) int   g_ecol  [N_EDGES];
__device__ __align__(16) float g_enorm [N_EDGES];
__device__ __align__(16) float g_h0    [(size_t)N_NODES * OUT_CH];
__device__ __align__(16) float g_h1    [(size_t)N_NODES * OUT_CH];

// ---------------- dtype probe + index conversion ----------------
// If the buffer holds int64 values < 2^31, every odd 32-bit word is 0.
// If it holds int32 node ids, odd words are random in [0,100000) -> nonzero.
__global__ void detect_kernel(const int* __restrict__ buf) {
    if (threadIdx.x == 0 && blockIdx.x == 0) {
        int any_odd_nonzero = 0;
        #pragma unroll 4
        for (int i = 0; i < 2048; i++) {
            if (buf[2 * i + 1] != 0) { any_odd_nonzero = 1; break; }
        }
        g_is64 = any_odd_nonzero ? 0 : 1;
    }
}

__global__ void convert_kernel(const void* __restrict__ buf) {
    int e = blockIdx.x * blockDim.x + threadIdx.x;
    if (e >= N_EDGES) return;
    if (g_is64) {
        const long long* p = (const long long*)buf;
        g_rows[e] = (int)p[e];
        g_cols[e] = (int)p[(size_t)N_EDGES + e];
    } else {
        const int* p = (const int*)buf;
        g_rows[e] = p[e];
        g_cols[e] = p[N_EDGES + e];
    }
}

// ---------------- CSR build ----------------
__global__ void zero_cnt_kernel() {
    int i = blockIdx.x * blockDim.x + threadIdx.x;
    if (i < N_NODES) g_cnt[i] = 0;
}

__global__ void hist_kernel() {
    int e = blockIdx.x * blockDim.x + threadIdx.x;
    if (e >= N_EDGES) return;
    int r = g_rows[e];
    int c = g_cols[e];
    if ((unsigned)r >= N_NODES || (unsigned)c >= N_NODES) return;
    if (r != c) atomicAdd(&g_cnt[r], 1);
}

__global__ void dinv_kernel() {
    int i = blockIdx.x * blockDim.x + threadIdx.x;
    if (i < N_NODES) g_dinv[i] = rsqrtf((float)g_cnt[i] + 1.0f);
}

// single-block exclusive scan over g_cnt -> g_rowptr (100k elems, 1024 thr)
__global__ void scan_kernel() {
    __shared__ int sums[1024];
    int t = threadIdx.x;
    const int CH = (N_NODES + 1023) / 1024;  // 98
    int s0 = t * CH;
    int s1 = s0 + CH;
    if (s0 > N_NODES) s0 = N_NODES;
    if (s1 > N_NODES) s1 = N_NODES;
    int sum = 0;
    for (int i = s0; i < s1; i++) sum += g_cnt[i];
    sums[t] = sum;
    __syncthreads();
    for (int off = 1; off < 1024; off <<= 1) {
        int v = (t >= off) ? sums[t - off] : 0;
        __syncthreads();
        sums[t] += v;
        __syncthreads();
    }
    int base = (t == 0) ? 0 : sums[t - 1];
    for (int i = s0; i < s1; i++) { g_rowptr[i] = base; base += g_cnt[i]; }
    if (t == 1023) g_rowptr[N_NODES] = base;
}

// scatter edges into CSR slots; per-edge norm = dinv[r]*dinv[c]
__global__ void scatter_kernel() {
    int e = blockIdx.x * blockDim.x + threadIdx.x;
    if (e >= N_EDGES) return;
    int r = g_rows[e];
    int c = g_cols[e];
    if ((unsigned)r >= N_NODES || (unsigned)c >= N_NODES) return;
    if (r == c) return;
    int pos = g_rowptr[r] + atomicAdd(&g_cnt[r], 1);
    g_ecol[pos]  = c;
    g_enorm[pos] = g_dinv[r] * g_dinv[c];
}

// ---------------- GEMM: g_h0 = x @ W  (fp32 SIMT, 128x64 tile) ----------------
#define BM 128
#define BK 16

__global__ __launch_bounds__(256) void gemm_xw_kernel(
    const float* __restrict__ x, const float* __restrict__ W) {
    __shared__ float xs[BK][BM];      // [k][m]
    __shared__ float ws[BK][OUT_CH];  // [k][n]

    int tid = threadIdx.x;
    int tx = tid & 15;   // 16 col groups * 4 cols = 64
    int ty = tid >> 4;   // 16 row groups * 8 rows = 128
    int m0 = blockIdx.x * BM;

    float acc[8][4];
    #pragma unroll
    for (int j = 0; j < 8; j++)
        #pragma unroll
        for (int i = 0; i < 4; i++) acc[j][i] = 0.0f;

    for (int k0 = 0; k0 < IN_CH; k0 += BK) {
        #pragma unroll
        for (int l = 0; l < 2; l++) {
            int idx = tid + l * 256;       // 0..511
            int row = idx >> 2;            // 0..127
            int cc  = (idx & 3) << 2;      // 0,4,8,12
            float4 v = make_float4(0.f, 0.f, 0.f, 0.f);
            if (m0 + row < N_NODES)
                v = *(const float4*)(x + (size_t)(m0 + row) * IN_CH + k0 + cc);
            xs[cc + 0][row] = v.x;
            xs[cc + 1][row] = v.y;
            xs[cc + 2][row] = v.z;
            xs[cc + 3][row] = v.w;
        }
        {
            int k  = tid >> 4;             // 0..15
            int cc = (tid & 15) << 2;      // 0..60
            float4 v = *(const float4*)(W + (size_t)(k0 + k) * OUT_CH + cc);
            *(float4*)&ws[k][cc] = v;
        }
        __syncthreads();

        #pragma unroll
        for (int kk = 0; kk < BK; kk++) {
            float4 b  = *(const float4*)&ws[kk][tx * 4];
            float4 a0 = *(const float4*)&xs[kk][ty * 8];
            float4 a1 = *(const float4*)&xs[kk][ty * 8 + 4];
            float a[8] = {a0.x, a0.y, a0.z, a0.w, a1.x, a1.y, a1.z, a1.w};
            #pragma unroll
            for (int j = 0; j < 8; j++) {
                acc[j][0] += a[j] * b.x;
                acc[j][1] += a[j] * b.y;
                acc[j][2] += a[j] * b.z;
                acc[j][3] += a[j] * b.w;
            }
        }
        __syncthreads();
    }

    #pragma unroll
    for (int j = 0; j < 8; j++) {
        int row = m0 + ty * 8 + j;
        if (row < N_NODES) {
            float4 v = make_float4(acc[j][0], acc[j][1], acc[j][2], acc[j][3]);
            *(float4*)(g_h0 + (size_t)row * OUT_CH + tx * 4) = v;
        }
    }
}

// ---------------- gather-based propagation (one warp per node) --------------
// MODE 0: hin = g_h0, hout = g_h1.  MODE 1: hin = g_h1, hout = outp.
template <int MODE>
__global__ __launch_bounds__(256) void gather_kernel(float* __restrict__ outp) {
    int node = (int)((blockIdx.x * blockDim.x + threadIdx.x) >> 5);
    if (node >= N_NODES) return;
    int lane = threadIdx.x & 31;

    const float* __restrict__ hin  = (MODE == 0) ? g_h0 : g_h1;
    float*       __restrict__ hout = (MODE == 0) ? g_h1 : outp;

    int start = g_rowptr[node];
    int end   = g_rowptr[node + 1];
    int c4 = (lane & 15) << 2;          // float4 column offset: 0..60

    float4 acc = make_float4(0.f, 0.f, 0.f, 0.f);
    // two edges per iteration: lanes 0-15 -> edge e, lanes 16-31 -> edge e+1
    for (int e = start + (lane >> 4); e < end; e += 2) {
        int   c   = g_ecol[e];
        float nrm = g_enorm[e];
        float4 v = *(const float4*)(hin + (size_t)c * OUT_CH + c4);
        acc.x += nrm * v.x;
        acc.y += nrm * v.y;
        acc.z += nrm * v.z;
        acc.w += nrm * v.w;
    }
    // combine the two half-warp partials (same columns)
    acc.x += __shfl_xor_sync(0xFFFFFFFFu, acc.x, 16);
    acc.y += __shfl_xor_sync(0xFFFFFFFFu, acc.y, 16);
    acc.z += __shfl_xor_sync(0xFFFFFFFFu, acc.z, 16);
    acc.w += __shfl_xor_sync(0xFFFFFFFFu, acc.w, 16);

    if (lane < 16) {
        float d = g_dinv[node];
        float s = d * d;
        float4 sv = *(const float4*)(hin + (size_t)node * OUT_CH + c4);
        acc.x += s * sv.x;
        acc.y += s * sv.y;
        acc.z += s * sv.z;
        acc.w += s * sv.w;
        *(float4*)(hout + (size_t)node * OUT_CH + c4) = acc;
    }
}

extern "C" void kernel_launch(void* const* d_in, const int* in_sizes, int n_in,
                              void* d_out, int out_size) {
    const void*  edge_index = d_in[0];               // [2, N_EDGES] int32 or int64
    const float* x          = (const float*)d_in[1]; // [N_NODES, 512]
    const float* W          = (const float*)d_in[2]; // [512, 64]
    float*       out        = (float*)d_out;         // [N_NODES, 64]

    // 0) dtype probe + conversion to int32 rows/cols
    detect_kernel<<<1, 32>>>((const int*)edge_index);
    convert_kernel<<<(N_EDGES + 255) / 256, 256>>>(edge_index);

    // 1) CSR build: histogram -> scan -> dinv -> scatter
    zero_cnt_kernel<<<(N_NODES + 255) / 256, 256>>>();
    hist_kernel<<<(N_EDGES + 255) / 256, 256>>>();
    scan_kernel<<<1, 1024>>>();
    dinv_kernel<<<(N_NODES + 255) / 256, 256>>>();
    zero_cnt_kernel<<<(N_NODES + 255) / 256, 256>>>();
    scatter_kernel<<<(N_EDGES + 255) / 256, 256>>>();

    // 2) g_h0 = x @ W
    gemm_xw_kernel<<<(N_NODES + BM - 1) / BM, 256>>>(x, W);

    // 3) two propagation hops (gather, warp per node)
    const int blocks = (N_NODES * 32 + 255) / 256;
    gather_kernel<0><<<blocks, 256>>>(nullptr);
    gather_kernel<1><<<blocks, 256>>>(out);
}

// round 5
// speedup vs baseline: 1.3423x; 1.3423x over previous
#include <cuda_runtime.h>
#include <cuda_bf16.h>
#include <cstdint>

#define N_NODES 100000
#define N_EDGES 3200000
#define IN_CH   512
#define OUT_CH  64

// ---- scratch: __device__ globals only (no allocations allowed) ----
__device__ int g_is64;
__device__ __align__(16) int   g_rows  [N_EDGES];
__device__ __align__(16) int   g_cols  [N_EDGES];
__device__ __align__(16) int   g_cnt   [N_NODES];
__device__ __align__(16) int   g_rowptr[N_NODES + 1];
__device__ __align__(16) float g_dinv  [N_NODES];
__device__ __align__(16) int   g_ecol  [N_EDGES];
__device__ __align__(16) float g_h0    [(size_t)N_NODES * OUT_CH];  // h0s = dinv * (xW)
__device__ __align__(16) float g_h1    [(size_t)N_NODES * OUT_CH];  // h1s = dinv * h1
// W pre-split into bf16 hi/lo, transposed to [n][k] so b32 pairs run along k
__device__ __align__(16) __nv_bfloat16 g_Wth[OUT_CH][IN_CH];
__device__ __align__(16) __nv_bfloat16 g_Wtl[OUT_CH][IN_CH];

// ---------------- dtype probe + index conversion ----------------
__global__ void detect_kernel(const int* __restrict__ buf) {
    if (threadIdx.x == 0 && blockIdx.x == 0) {
        int any_odd_nonzero = 0;
        for (int i = 0; i < 2048; i++) {
            if (buf[2 * i + 1] != 0) { any_odd_nonzero = 1; break; }
        }
        g_is64 = any_odd_nonzero ? 0 : 1;
    }
}

__global__ void convert_kernel(const void* __restrict__ buf) {
    int e = blockIdx.x * blockDim.x + threadIdx.x;
    if (e >= N_EDGES) return;
    if (g_is64) {
        const long long* p = (const long long*)buf;
        g_rows[e] = (int)p[e];
        g_cols[e] = (int)p[(size_t)N_EDGES + e];
    } else {
        const int* p = (const int*)buf;
        g_rows[e] = p[e];
        g_cols[e] = p[N_EDGES + e];
    }
}

// ---------------- CSR build ----------------
__global__ void zero_cnt_kernel() {
    int i = blockIdx.x * blockDim.x + threadIdx.x;
    if (i < N_NODES) g_cnt[i] = 0;
}

__global__ void hist_kernel() {
    int e = blockIdx.x * blockDim.x + threadIdx.x;
    if (e >= N_EDGES) return;
    int r = g_rows[e];
    int c = g_cols[e];
    if ((unsigned)r >= N_NODES || (unsigned)c >= N_NODES) return;
    if (r != c) atomicAdd(&g_cnt[r], 1);
}

__global__ void dinv_kernel() {
    int i = blockIdx.x * blockDim.x + threadIdx.x;
    if (i < N_NODES) g_dinv[i] = rsqrtf((float)g_cnt[i] + 1.0f);
}

__global__ void scan_kernel() {
    __shared__ int sums[1024];
    int t = threadIdx.x;
    const int CH = (N_NODES + 1023) / 1024;  // 98
    int s0 = t * CH;
    int s1 = s0 + CH;
    if (s0 > N_NODES) s0 = N_NODES;
    if (s1 > N_NODES) s1 = N_NODES;
    int sum = 0;
    for (int i = s0; i < s1; i++) sum += g_cnt[i];
    sums[t] = sum;
    __syncthreads();
    for (int off = 1; off < 1024; off <<= 1) {
        int v = (t >= off) ? sums[t - off] : 0;
        __syncthreads();
        sums[t] += v;
        __syncthreads();
    }
    int base = (t == 0) ? 0 : sums[t - 1];
    for (int i = s0; i < s1; i++) { g_rowptr[i] = base; base += g_cnt[i]; }
    if (t == 1023) g_rowptr[N_NODES] = base;
}

__global__ void scatter_kernel() {
    int e = blockIdx.x * blockDim.x + threadIdx.x;
    if (e >= N_EDGES) return;
    int r = g_rows[e];
    int c = g_cols[e];
    if ((unsigned)r >= N_NODES || (unsigned)c >= N_NODES) return;
    if (r == c) return;
    int pos = g_rowptr[r] + atomicAdd(&g_cnt[r], 1);
    g_ecol[pos] = c;
}

// ---------------- W split/transpose (tiny, once) ----------------
__global__ void wsplit_kernel(const float* __restrict__ W) {
    int t = blockIdx.x * blockDim.x + threadIdx.x;   // 32768
    if (t >= IN_CH * OUT_CH) return;
    int n = t / IN_CH;
    int k = t % IN_CH;
    float v = W[(size_t)k * OUT_CH + n];
    __nv_bfloat16 hi = __float2bfloat16(v);
    __nv_bfloat16 lo = __float2bfloat16(v - __bfloat162float(hi));
    g_Wth[n][k] = hi;
    g_Wtl[n][k] = lo;
}

// ---------------- GEMM: g_h0 = dinv ⊙ (x @ W) via bf16-split mma.sync ------
#define GBM 128
#define GBK 32
#define SAS 17   // b32 pairs per smem row (16 + 1 pad)

__device__ __forceinline__ uint32_t pack_bf16(__nv_bfloat16 a, __nv_bfloat16 b) {
    return (uint32_t)__bfloat16_as_ushort(a) | ((uint32_t)__bfloat16_as_ushort(b) << 16);
}

__device__ __forceinline__ void mma16816(float c[4], const uint32_t a[4],
                                         const uint32_t b[2]) {
    asm volatile(
        "mma.sync.aligned.m16n8k16.row.col.f32.bf16.bf16.f32 "
        "{%0,%1,%2,%3}, {%4,%5,%6,%7}, {%8,%9}, {%0,%1,%2,%3};"
        : "+f"(c[0]), "+f"(c[1]), "+f"(c[2]), "+f"(c[3])
        : "r"(a[0]), "r"(a[1]), "r"(a[2]), "r"(a[3]), "r"(b[0]), "r"(b[1]));
}

__global__ __launch_bounds__(256, 2) void gemm_mma_kernel(const float* __restrict__ x) {
    __shared__ uint32_t sAh[GBM][SAS];
    __shared__ uint32_t sAl[GBM][SAS];
    __shared__ uint32_t sBh[OUT_CH][SAS];
    __shared__ uint32_t sBl[OUT_CH][SAS];

    int tid  = threadIdx.x;
    int wid  = tid >> 5, lane = tid & 31;
    int wm   = wid & 3,  wn   = wid >> 2;       // 4 m-warps x 2 n-warps
    int grp  = lane >> 2, t4  = lane & 3;
    int m0   = blockIdx.x * GBM;

    float c[2][4][4];
    #pragma unroll
    for (int i = 0; i < 2; i++)
        #pragma unroll
        for (int j = 0; j < 4; j++)
            #pragma unroll
            for (int k = 0; k < 4; k++) c[i][j][k] = 0.0f;

    for (int k0 = 0; k0 < IN_CH; k0 += GBK) {
        // x tile: 128 rows x 32 k, split to bf16 hi/lo in-flight
        #pragma unroll
        for (int i = 0; i < 4; i++) {
            int idx = tid + i * 256;     // 0..1023 (float4 index)
            int row = idx >> 3;          // 8 float4 per row
            int f4  = idx & 7;
            float4 v = make_float4(0.f, 0.f, 0.f, 0.f);
            if (m0 + row < N_NODES)
                v = *(const float4*)(x + (size_t)(m0 + row) * IN_CH + k0 + f4 * 4);
            __nv_bfloat16 hx = __float2bfloat16(v.x);
            __nv_bfloat16 hy = __float2bfloat16(v.y);
            __nv_bfloat16 hz = __float2bfloat16(v.z);
            __nv_bfloat16 hw = __float2bfloat16(v.w);
            sAh[row][f4 * 2]     = pack_bf16(hx, hy);
            sAh[row][f4 * 2 + 1] = pack_bf16(hz, hw);
            __nv_bfloat16 lx = __float2bfloat16(v.x - __bfloat162float(hx));
            __nv_bfloat16 ly = __float2bfloat16(v.y - __bfloat162float(hy));
            __nv_bfloat16 lz = __float2bfloat16(v.z - __bfloat162float(hz));
            __nv_bfloat16 lw = __float2bfloat16(v.w - __bfloat162float(hw));
            sAl[row][f4 * 2]     = pack_bf16(lx, ly);
            sAl[row][f4 * 2 + 1] = pack_bf16(lz, lw);
        }
        // W tile from pre-split globals: 64 n-rows x 16 b32 (k pairs)
        #pragma unroll
        for (int i = 0; i < 4; i++) {
            int idx = tid + i * 256;     // 0..1023
            int n  = idx >> 4;
            int kp = idx & 15;
            sBh[n][kp] = ((const uint32_t*)&g_Wth[n][k0])[kp];
            sBl[n][kp] = ((const uint32_t*)&g_Wtl[n][k0])[kp];
        }
        __syncthreads();

        #pragma unroll
        for (int kt = 0; kt < 2; kt++) {
            int kp0 = kt * 8;
            uint32_t ah[2][4], al[2][4];
            #pragma unroll
            for (int mt = 0; mt < 2; mt++) {
                int r = wm * 32 + mt * 16 + grp;
                ah[mt][0] = sAh[r][kp0 + t4];
                ah[mt][1] = sAh[r + 8][kp0 + t4];
                ah[mt][2] = sAh[r][kp0 + t4 + 4];
                ah[mt][3] = sAh[r + 8][kp0 + t4 + 4];
                al[mt][0] = sAl[r][kp0 + t4];
                al[mt][1] = sAl[r + 8][kp0 + t4];
                al[mt][2] = sAl[r][kp0 + t4 + 4];
                al[mt][3] = sAl[r + 8][kp0 + t4 + 4];
            }
            uint32_t bh[4][2], bl[4][2];
            #pragma unroll
            for (int nt = 0; nt < 4; nt++) {
                int n = wn * 32 + nt * 8 + grp;
                bh[nt][0] = sBh[n][kp0 + t4];
                bh[nt][1] = sBh[n][kp0 + t4 + 4];
                bl[nt][0] = sBl[n][kp0 + t4];
                bl[nt][1] = sBl[n][kp0 + t4 + 4];
            }
            #pragma unroll
            for (int mt = 0; mt < 2; mt++)
                #pragma unroll
                for (int nt = 0; nt < 4; nt++) {
                    mma16816(c[mt][nt], ah[mt], bh[nt]);
                    mma16816(c[mt][nt], ah[mt], bl[nt]);
                    mma16816(c[mt][nt], al[mt], bh[nt]);
                }
        }
        __syncthreads();
    }

    // epilogue: scale by dinv, store h0s
    #pragma unroll
    for (int mt = 0; mt < 2; mt++) {
        int r0 = m0 + wm * 32 + mt * 16 + grp;
        int r1 = r0 + 8;
        float d0 = (r0 < N_NODES) ? g_dinv[r0] : 0.0f;
        float d1 = (r1 < N_NODES) ? g_dinv[r1] : 0.0f;
        #pragma unroll
        for (int nt = 0; nt < 4; nt++) {
            int col = wn * 32 + nt * 8 + t4 * 2;
            if (r0 < N_NODES) {
                float2 v = make_float2(c[mt][nt][0] * d0, c[mt][nt][1] * d0);
                *(float2*)(g_h0 + (size_t)r0 * OUT_CH + col) = v;
            }
            if (r1 < N_NODES) {
                float2 v = make_float2(c[mt][nt][2] * d1, c[mt][nt][3] * d1);
                *(float2*)(g_h0 + (size_t)r1 * OUT_CH + col) = v;
            }
        }
    }
}

// ---------------- gather-based propagation (one warp per node) --------------
// out[r] = scale * (sum_{c in N(r)} hin[c] + hin[r])
// MODE 0: hin=g_h0 (h0s), hout=g_h1, scale=d^2  -> h1s
// MODE 1: hin=g_h1 (h1s), hout=outp, scale=d    -> h2 (final)
template <int MODE>
__global__ __launch_bounds__(256) void gather_kernel(float* __restrict__ outp) {
    int node = (int)((blockIdx.x * blockDim.x + threadIdx.x) >> 5);
    if (node >= N_NODES) return;
    int lane = threadIdx.x & 31;

    const float* __restrict__ hin  = (MODE == 0) ? g_h0 : g_h1;
    float*       __restrict__ hout = (MODE == 0) ? g_h1 : outp;

    int start = g_rowptr[node];
    int end   = g_rowptr[node + 1];
    int c4 = (lane & 15) << 2;          // float4 column offset: 0..60

    float4 acc = make_float4(0.f, 0.f, 0.f, 0.f);
    for (int e = start + (lane >> 4); e < end; e += 2) {
        int c = g_ecol[e];
        float4 v = *(const float4*)(hin + (size_t)c * OUT_CH + c4);
        acc.x += v.x; acc.y += v.y; acc.z += v.z; acc.w += v.w;
    }
    acc.x += __shfl_xor_sync(0xFFFFFFFFu, acc.x, 16);
    acc.y += __shfl_xor_sync(0xFFFFFFFFu, acc.y, 16);
    acc.z += __shfl_xor_sync(0xFFFFFFFFu, acc.z, 16);
    acc.w += __shfl_xor_sync(0xFFFFFFFFu, acc.w, 16);

    if (lane < 16) {
        float d = g_dinv[node];
        float s = (MODE == 0) ? d * d : d;
        float4 sv = *(const float4*)(hin + (size_t)node * OUT_CH + c4);
        acc.x = s * (acc.x + sv.x);
        acc.y = s * (acc.y + sv.y);
        acc.z = s * (acc.z + sv.z);
        acc.w = s * (acc.w + sv.w);
        *(float4*)(hout + (size_t)node * OUT_CH + c4) = acc;
    }
}

extern "C" void kernel_launch(void* const* d_in, const int* in_sizes, int n_in,
                              void* d_out, int out_size) {
    const void*  edge_index = d_in[0];               // [2, N_EDGES] int32 or int64
    const float* x          = (const float*)d_in[1]; // [N_NODES, 512]
    const float* W          = (const float*)d_in[2]; // [512, 64]
    float*       out        = (float*)d_out;         // [N_NODES, 64]

    // 0) dtype probe + conversion to int32 rows/cols
    detect_kernel<<<1, 32>>>((const int*)edge_index);
    convert_kernel<<<(N_EDGES + 255) / 256, 256>>>(edge_index);

    // 1) CSR build
    zero_cnt_kernel<<<(N_NODES + 255) / 256, 256>>>();
    hist_kernel<<<(N_EDGES + 255) / 256, 256>>>();
    scan_kernel<<<1, 1024>>>();
    dinv_kernel<<<(N_NODES + 255) / 256, 256>>>();
    zero_cnt_kernel<<<(N_NODES + 255) / 256, 256>>>();
    scatter_kernel<<<(N_EDGES + 255) / 256, 256>>>();

    // 2) W split (tiny) + GEMM with dinv epilogue -> g_h0 = h0s
    wsplit_kernel<<<(IN_CH * OUT_CH + 255) / 256, 256>>>(W);
    gemm_mma_kernel<<<(N_NODES + GBM - 1) / GBM, 256>>>(x);

    // 3) two propagation hops (gather, warp per node)
    const int blocks = (N_NODES * 32 + 255) / 256;
    gather_kernel<0><<<blocks, 256>>>(nullptr);
    gather_kernel<1><<<blocks, 256>>>(out);
}